// round 16
// baseline (speedup 1.0000x reference)
#include <cuda_runtime.h>
#include <cuda_fp16.h>
#include <math.h>

#define Bn 4
#define Sn 4096
#define Dn 256
#define Mrows (Bn*Sn)   // 16384
#define NIT  (Sn/32)    // 128

// -------- scratch (device globals; allocation-free rule) --------
__device__ __align__(16) __half   g_vph[(size_t)Mrows * Dn];
__device__ __align__(16) __half   g_ph [(size_t)Bn * Sn * Sn];   // exp(logit), fp16
__device__ __align__(16) float    g_pre[(size_t)Mrows * Dn];
__device__ __align__(16) unsigned g_sqbits[Mrows * 8];
__device__ __align__(16) unsigned g_skbits[Mrows * 8];
__device__ __align__(16) float    g_rowsum4[4][Mrows];
__device__ __align__(16) __half   g_wh[4][Dn * Dn];
__device__ __align__(16) __half   g_wl[4][Dn * Dn];

__device__ __forceinline__ unsigned s2u(const void* p) {
    return (unsigned)__cvta_generic_to_shared(p);
}

#define LDMX4(r0,r1,r2,r3,addr) \
    asm volatile("ldmatrix.sync.aligned.m8n8.x4.shared.b16 {%0,%1,%2,%3}, [%4];" \
        : "=r"(r0),"=r"(r1),"=r"(r2),"=r"(r3) : "r"(addr))
#define LDMX4T(r0,r1,r2,r3,addr) \
    asm volatile("ldmatrix.sync.aligned.m8n8.x4.trans.shared.b16 {%0,%1,%2,%3}, [%4];" \
        : "=r"(r0),"=r"(r1),"=r"(r2),"=r"(r3) : "r"(addr))
#define MMA16816(C,A0,A1,A2,A3,B0,B1) \
    asm volatile("mma.sync.aligned.m16n8k16.row.col.f32.f16.f16.f32 " \
        "{%0,%1,%2,%3}, {%4,%5,%6,%7}, {%8,%9}, {%0,%1,%2,%3};" \
        : "+f"(C[0]),"+f"(C[1]),"+f"(C[2]),"+f"(C[3]) \
        : "r"(A0),"r"(A1),"r"(A2),"r"(A3), "r"(B0),"r"(B1))

// ============================================================
// Pre-split the 4 weight matrices into hi/lo fp16 halves
// ============================================================
__global__ void wsplit_kernel(const float* __restrict__ w0, const float* __restrict__ w1,
                              const float* __restrict__ w2, const float* __restrict__ w3)
{
    const int idx = blockIdx.x * 256 + threadIdx.x;
    const float* ws[4] = {w0, w1, w2, w3};
    #pragma unroll
    for (int m = 0; m < 4; m++) {
        const float x = ws[m][idx];
        const __half h = __float2half_rn(x);
        g_wh[m][idx] = h;
        g_wl[m][idx] = __float2half_rn(x - __half2float(h));
    }
}

// ============================================================
// shared GEMM mainloop pieces (split-fp16, m16n8k16)
// CTA = 128m x 128n, 8 warps (4m x 2n), k-step 32.
// ============================================================
#define LDA 40    // A smem pitch (halfs)
#define LDW 136   // W smem pitch (halfs)

#define GEMM_STAGE_A(A, DO_TANH) \
    _Pragma("unroll") \
    for (int i = 0; i < 4; i++) { \
        const int u = t + 256 * i, row = u >> 3, c4 = (u & 7) << 2; \
        const size_t gidx = (size_t)(m0 + row) * Dn + k0 + c4; \
        float4 f = *(const float4*)&(A)[gidx]; \
        if (DO_TANH) { \
            const float4 an = *(const float4*)&anchor[gidx & (size_t)(Sn * Dn - 1)]; \
            f.x = tanhf(f.x * an.x); f.y = tanhf(f.y * an.y); \
            f.z = tanhf(f.z * an.z); f.w = tanhf(f.w * an.w); \
        } \
        const __half h0 = __float2half_rn(f.x), h1 = __float2half_rn(f.y), \
                     h2 = __float2half_rn(f.z), h3 = __float2half_rn(f.w); \
        uint2 hi, lo; \
        hi.x = (unsigned)__half_as_ushort(h0) | ((unsigned)__half_as_ushort(h1) << 16); \
        hi.y = (unsigned)__half_as_ushort(h2) | ((unsigned)__half_as_ushort(h3) << 16); \
        const __half l0 = __float2half_rn(f.x - __half2float(h0)), \
                     l1 = __float2half_rn(f.y - __half2float(h1)), \
                     l2 = __float2half_rn(f.z - __half2float(h2)), \
                     l3 = __float2half_rn(f.w - __half2float(h3)); \
        lo.x = (unsigned)__half_as_ushort(l0) | ((unsigned)__half_as_ushort(l1) << 16); \
        lo.y = (unsigned)__half_as_ushort(l2) | ((unsigned)__half_as_ushort(l3) << 16); \
        *(uint2*)&Ah[row][c4] = hi; \
        *(uint2*)&Al[row][c4] = lo; \
    }

#define GEMM_STAGE_W(WH, WL) \
    _Pragma("unroll") \
    for (int i = 0; i < 2; i++) { \
        const int u = t + 256 * i, row = u >> 4, c8 = (u & 15) << 3; \
        *(uint4*)&Wh[row][c8] = *(const uint4*)&(WH)[(size_t)(k0 + row) * Dn + n0 + c8]; \
        *(uint4*)&Wl[row][c8] = *(const uint4*)&(WL)[(size_t)(k0 + row) * Dn + n0 + c8]; \
    }

#define GEMM_MMA_BODY() { \
    const unsigned Ah_b = s2u(&Ah[0][0]), Al_b = s2u(&Al[0][0]); \
    const unsigned Wh_b = s2u(&Wh[0][0]), Wl_b = s2u(&Wl[0][0]); \
    _Pragma("unroll") \
    for (int kt = 0; kt < 2; kt++) { \
        unsigned ah0[4], ah1[4], al0[4], al1[4]; \
        const unsigned arow = (wm * 32 + (lane & 15)) * (LDA * 2) \
                            + (kt * 16 + (lane >> 4) * 8) * 2; \
        LDMX4(ah0[0], ah0[1], ah0[2], ah0[3], Ah_b + arow); \
        LDMX4(ah1[0], ah1[1], ah1[2], ah1[3], Ah_b + arow + 16 * (LDA * 2)); \
        LDMX4(al0[0], al0[1], al0[2], al0[3], Al_b + arow); \
        LDMX4(al1[0], al1[1], al1[2], al1[3], Al_b + arow + 16 * (LDA * 2)); \
        _Pragma("unroll") \
        for (int np = 0; np < 4; np++) { \
            unsigned bh[4], bl[4]; \
            const unsigned baddr = (kt * 16 + (lane & 15)) * (LDW * 2) \
                                 + (wn * 64 + np * 16 + (lane >> 4) * 8) * 2; \
            LDMX4T(bh[0], bh[1], bh[2], bh[3], Wh_b + baddr); \
            LDMX4T(bl[0], bl[1], bl[2], bl[3], Wl_b + baddr); \
            MMA16816(acc[0][np*2+0], ah0[0],ah0[1],ah0[2],ah0[3], bh[0],bh[1]); \
            MMA16816(acc[0][np*2+1], ah0[0],ah0[1],ah0[2],ah0[3], bh[2],bh[3]); \
            MMA16816(acc[1][np*2+0], ah1[0],ah1[1],ah1[2],ah1[3], bh[0],bh[1]); \
            MMA16816(acc[1][np*2+1], ah1[0],ah1[1],ah1[2],ah1[3], bh[2],bh[3]); \
            MMA16816(acc[0][np*2+0], ah0[0],ah0[1],ah0[2],ah0[3], bl[0],bl[1]); \
            MMA16816(acc[0][np*2+1], ah0[0],ah0[1],ah0[2],ah0[3], bl[2],bl[3]); \
            MMA16816(acc[1][np*2+0], ah1[0],ah1[1],ah1[2],ah1[3], bl[0],bl[1]); \
            MMA16816(acc[1][np*2+1], ah1[0],ah1[1],ah1[2],ah1[3], bl[2],bl[3]); \
            MMA16816(acc[0][np*2+0], al0[0],al0[1],al0[2],al0[3], bh[0],bh[1]); \
            MMA16816(acc[0][np*2+1], al0[0],al0[1],al0[2],al0[3], bh[2],bh[3]); \
            MMA16816(acc[1][np*2+0], al1[0],al1[1],al1[2],al1[3], bh[0],bh[1]); \
            MMA16816(acc[1][np*2+1], al1[0],al1[1],al1[2],al1[3], bh[2],bh[3]); \
        } \
    } }

// ---- q/k/v projections, merged: blockIdx.z selects which ----
__global__ __launch_bounds__(256, 2) void proj_mma(
    const float* __restrict__ Aq, const float* __restrict__ Ak, const float* __restrict__ Av,
    const float* __restrict__ bq, const float* __restrict__ bk, const float* __restrict__ bv,
    unsigned* __restrict__ oSq, unsigned* __restrict__ oSk, __half* __restrict__ oVh)
{
    __shared__ __align__(16) __half Ah[128][LDA], Al[128][LDA];
    __shared__ __align__(16) __half Wh[32][LDW], Wl[32][LDW];

    const int t = threadIdx.x, lane = t & 31, wid = t >> 5;
    const int wm = wid >> 1, wn = wid & 1;
    const int m0 = blockIdx.y * 128, n0 = blockIdx.x * 128;
    const int z  = blockIdx.z;
    const float* anchor = nullptr;   // referenced (dead) by GEMM_STAGE_A(A, false)

    const float* A    = (z == 0) ? Aq : (z == 1) ? Ak : Av;
    const float* bias = (z == 0) ? bq : (z == 1) ? bk : bv;
    unsigned* outBits = (z == 0) ? oSq : oSk;
    const __half* WH = g_wh[z];
    const __half* WL = g_wl[z];

    float acc[2][8][4];
    #pragma unroll
    for (int m = 0; m < 2; m++)
        #pragma unroll
        for (int n = 0; n < 8; n++)
            #pragma unroll
            for (int j = 0; j < 4; j++) acc[m][n][j] = 0.f;

    for (int k0 = 0; k0 < Dn; k0 += 32) {
        __syncthreads();
        GEMM_STAGE_A(A, false)
        GEMM_STAGE_W(WH, WL)
        __syncthreads();
        GEMM_MMA_BODY()
    }

    #pragma unroll
    for (int m = 0; m < 2; m++) {
        #pragma unroll
        for (int j2 = 0; j2 < 2; j2++) {
            const int row = m0 + wm * 32 + m * 16 + (lane >> 2) + j2 * 8;
            unsigned wv[2] = {0u, 0u};
            #pragma unroll
            for (int n = 0; n < 8; n++) {
                const int cl  = wn * 64 + n * 8 + ((lane & 3) << 1);
                const int col = n0 + cl;
                const float2 bv2 = *(const float2*)&bias[col];
                const float x0 = acc[m][n][j2 * 2 + 0] + bv2.x;
                const float x1 = acc[m][n][j2 * 2 + 1] + bv2.y;
                if (z == 2) {
                    unsigned p;
                    asm("cvt.rn.f16x2.f32 %0, %1, %2;" : "=r"(p) : "f"(x1), "f"(x0));
                    *(unsigned*)&oVh[(size_t)row * Dn + col] = p;
                } else {
                    const int bit = ((n & 3) * 8) + ((lane & 3) << 1);
                    if (x0 < 0.f) wv[n >> 2] |= 1u << bit;
                    if (x1 < 0.f) wv[n >> 2] |= 1u << (bit + 1);
                }
            }
            if (z != 2) {
                const int wordb = (n0 + wn * 64) >> 5;
                if (wv[0]) atomicOr(&outBits[row * 8 + wordb + 0], wv[0]);
                if (wv[1]) atomicOr(&outBits[row * 8 + wordb + 1], wv[1]);
            }
        }
    }
}

// ---- dense: out = tanh(g_pre*anchor) @ dense_k + dense_b ----
__global__ __launch_bounds__(256, 2) void dense_mma(
    const float* __restrict__ A, const float* __restrict__ bias,
    float* __restrict__ outF, const float* __restrict__ anchor)
{
    __shared__ __align__(16) __half Ah[128][LDA], Al[128][LDA];
    __shared__ __align__(16) __half Wh[32][LDW], Wl[32][LDW];

    const int t = threadIdx.x, lane = t & 31, wid = t >> 5;
    const int wm = wid >> 1, wn = wid & 1;
    const int m0 = blockIdx.y * 128, n0 = blockIdx.x * 128;

    const __half* WH = g_wh[3];
    const __half* WL = g_wl[3];

    float acc[2][8][4];
    #pragma unroll
    for (int m = 0; m < 2; m++)
        #pragma unroll
        for (int n = 0; n < 8; n++)
            #pragma unroll
            for (int j = 0; j < 4; j++) acc[m][n][j] = 0.f;

    for (int k0 = 0; k0 < Dn; k0 += 32) {
        __syncthreads();
        GEMM_STAGE_A(A, true)
        GEMM_STAGE_W(WH, WL)
        __syncthreads();
        GEMM_MMA_BODY()
    }

    #pragma unroll
    for (int m = 0; m < 2; m++) {
        #pragma unroll
        for (int j2 = 0; j2 < 2; j2++) {
            const int row = m0 + wm * 32 + m * 16 + (lane >> 2) + j2 * 8;
            #pragma unroll
            for (int n = 0; n < 8; n++) {
                const int col = n0 + wn * 64 + n * 8 + ((lane & 3) << 1);
                const float2 bv2 = *(const float2*)&bias[col];
                *(float2*)&outF[(size_t)row * Dn + col] =
                    make_float2(acc[m][n][j2*2+0] + bv2.x, acc[m][n][j2*2+1] + bv2.y);
            }
        }
    }
}

// ============================================================
// psum: p[b,k,q] = exp((256-popc)/512)  (fp16 -> g_ph)   AND
//       g_rowsum4[qsel][b,k] = sum_{q in quarter} p   (fp32)
// grid (128 ktiles, 4 qsel, Bn); 256 thr; each thread owns 1 q-col
// per 256-block, k fully unrolled in registers.
// ============================================================
__global__ __launch_bounds__(256) void psum_kernel()
{
    __shared__ __align__(16) unsigned skt[32][8];
    __shared__ float red[32][8];
    const int t    = threadIdx.x;
    const int b    = blockIdx.z;
    const int k0   = blockIdx.x * 32;
    const int qsel = blockIdx.y;
    const size_t bS = (size_t)b * Sn;

    if (t < 64) ((uint4*)skt)[t] = ((const uint4*)&g_skbits[(bS + k0) * 8])[t];
    __syncthreads();

    float acc[32];
    #pragma unroll
    for (int k = 0; k < 32; k++) acc[k] = 0.f;

    for (int qs = 0; qs < 4; qs++) {
        const int q = qsel * 1024 + qs * 256 + t;
        const uint4* sqp = (const uint4*)&g_sqbits[(bS + q) * 8];
        const uint4 sq0 = sqp[0], sq1 = sqp[1];
        #pragma unroll
        for (int k = 0; k < 32; k++) {
            const uint4 s0 = *(const uint4*)&skt[k][0];
            const uint4 s1 = *(const uint4*)&skt[k][4];
            const int pc = __popc(s0.x ^ sq0.x) + __popc(s0.y ^ sq0.y)
                         + __popc(s0.z ^ sq0.z) + __popc(s0.w ^ sq0.w)
                         + __popc(s1.x ^ sq1.x) + __popc(s1.y ^ sq1.y)
                         + __popc(s1.z ^ sq1.z) + __popc(s1.w ^ sq1.w);
            const float p = __expf((float)(256 - pc) * (1.0f / 512.0f));
            acc[k] += p;
            g_ph[(bS + k0 + k) * Sn + q] = __float2half_rn(p);
        }
    }

    #pragma unroll
    for (int k = 0; k < 32; k++) {
        float v = acc[k];
        v += __shfl_xor_sync(0xFFFFFFFFu, v, 16);
        v += __shfl_xor_sync(0xFFFFFFFFu, v, 8);
        v += __shfl_xor_sync(0xFFFFFFFFu, v, 4);
        v += __shfl_xor_sync(0xFFFFFFFFu, v, 2);
        v += __shfl_xor_sync(0xFFFFFFFFu, v, 1);
        if ((t & 31) == 0) red[k][t >> 5] = v;
    }
    __syncthreads();
    if (t < 32)
        g_rowsum4[qsel][bS + k0 + t] =
            ((red[t][0] + red[t][1]) + (red[t][2] + red[t][3]))
          + ((red[t][4] + red[t][5]) + (red[t][6] + red[t][7]));
}

// ============================================================
// Fused attn + AV mma, single-barrier pipeline; p loaded from g_ph.
// ============================================================
#define LDD 264
#define LDK 40

__global__ __launch_bounds__(256, 2) void attn_mma_kernel(
    const float* __restrict__ mask, float* __restrict__ attn_out)
{
    __shared__ __align__(16) __half vp_s[2][32][LDD];  // 33792 B
    __shared__ __align__(16) __half ats[2][64][LDK];   // 10240 B
    __shared__ float inv_rs[2][32];                    //   256 B  (44288 total)

    const int t    = threadIdx.x;
    const int b    = blockIdx.y;
    const int q0   = blockIdx.x * 64;
    const int lane = t & 31, wid = t >> 5;
    const int wq   = wid >> 2, wd = wid & 3;
    const int qq   = t & 63, g = t >> 6;
    const size_t bS = (size_t)b * Sn;

    float acc[2][8][4];
    #pragma unroll
    for (int m = 0; m < 2; m++)
        #pragma unroll
        for (int n = 0; n < 8; n++)
            #pragma unroll
            for (int j = 0; j < 4; j++) acc[m][n][j] = 0.f;

    uint4 vpr[4]; float invr = 0.f;
    float  mrg0[8], mrg1[8];
    __half prg0[8], prg1[8];

#define A_LDG_VP(TILE) { \
    const uint4* vg = (const uint4*)&g_vph[(bS + (TILE) * 32) * Dn]; \
    _Pragma("unroll") for (int i = 0; i < 4; i++) vpr[i] = vg[t + 256 * i]; }
#define A_STS_VP(BUF) { \
    _Pragma("unroll") for (int i = 0; i < 4; i++) { \
        const int u = t + 256 * i; \
        *(uint4*)&vp_s[BUF][u >> 5][(u & 31) << 3] = vpr[i]; } }
#define A_LDG_INV(TILE) { \
    if (t < 32) { const size_t r = bS + (TILE) * 32 + t; \
        invr = 1.0f / (g_rowsum4[0][r] + g_rowsum4[1][r] + g_rowsum4[2][r] + g_rowsum4[3][r]); } }
#define A_STS_INV(BUF) { if (t < 32) inv_rs[BUF][t] = invr; }
#define A_LDG_MASK(TILE, MRG, PRG) { \
    _Pragma("unroll") for (int r = 0; r < 4; r++) { \
        _Pragma("unroll") for (int j = 0; j < 2; j++) { \
            const int kk = 2 * g + (r << 3) + j; \
            const size_t e = (bS + (TILE) * 32 + kk) * Sn + q0 + qq; \
            MRG[r * 2 + j] = mask[e]; \
            PRG[r * 2 + j] = g_ph[e]; } } }
#define A_SCALE(TILE, BUF, MRG, PRG) { \
    _Pragma("unroll") for (int r = 0; r < 4; r++) { \
        const int kk = 2 * g + (r << 3); \
        float a2[2]; \
        _Pragma("unroll") for (int j = 0; j < 2; j++) { \
            const float a = __half2float(PRG[r * 2 + j]) \
                          * inv_rs[BUF][kk + j] * MRG[r * 2 + j]; \
            a2[j] = a; \
            attn_out[(bS + (TILE) * 32 + kk + j) * Sn + q0 + qq] = a; } \
        unsigned p; \
        asm("cvt.rn.f16x2.f32 %0, %1, %2;" : "=r"(p) : "f"(a2[1]), "f"(a2[0])); \
        *(unsigned*)&ats[BUF][qq][kk] = p; } }
#define A_MMA(BUF) { \
    const unsigned ats_b = s2u(&ats[BUF][0][0]); \
    const unsigned vp_b  = s2u(&vp_s[BUF][0][0]); \
    _Pragma("unroll") for (int kt = 0; kt < 2; kt++) { \
        unsigned a0[4], a1[4]; \
        const unsigned acol = (kt * 16 + (lane >> 4) * 8) * 2; \
        LDMX4(a0[0], a0[1], a0[2], a0[3], \
              ats_b + (wq * 32 + (lane & 15)) * (LDK * 2) + acol); \
        LDMX4(a1[0], a1[1], a1[2], a1[3], \
              ats_b + (wq * 32 + 16 + (lane & 15)) * (LDK * 2) + acol); \
        _Pragma("unroll") for (int np = 0; np < 4; np++) { \
            unsigned bf[4]; \
            LDMX4T(bf[0], bf[1], bf[2], bf[3], \
                   vp_b + (kt * 16 + (lane & 15)) * (LDD * 2) \
                        + (wd * 64 + np * 16 + (lane >> 4) * 8) * 2); \
            MMA16816(acc[0][np * 2 + 0], a0[0], a0[1], a0[2], a0[3], bf[0], bf[1]); \
            MMA16816(acc[0][np * 2 + 1], a0[0], a0[1], a0[2], a0[3], bf[2], bf[3]); \
            MMA16816(acc[1][np * 2 + 0], a1[0], a1[1], a1[2], a1[3], bf[0], bf[1]); \
            MMA16816(acc[1][np * 2 + 1], a1[0], a1[1], a1[2], a1[3], bf[2], bf[3]); } } }
#define A_INTERVAL(IT, CUR, NXT, MRGNXT, PRGNXT, MRGCUR, PRGCUR) { \
    A_STS_VP(NXT) \
    if ((IT) + 2 < NIT) { A_STS_INV(CUR) } \
    if ((IT) + 2 < NIT) { A_LDG_VP((IT) + 2) } \
    if ((IT) + 3 < NIT) { A_LDG_INV((IT) + 3) } \
    if ((IT) + 2 < NIT) { A_LDG_MASK((IT) + 2, MRGCUR, PRGCUR) } \
    A_MMA(CUR) \
    A_SCALE((IT) + 1, NXT, MRGNXT, PRGNXT) \
    __syncthreads(); }

    // ---- prologue ----
    A_LDG_VP(0)  A_LDG_INV(0)  A_LDG_MASK(0, mrg0, prg0)
    A_STS_VP(0)  A_STS_INV(0)
    A_LDG_VP(1)  A_LDG_INV(1)  A_LDG_MASK(1, mrg1, prg1)
    __syncthreads();                 // vp[0], inv[0] visible
    A_SCALE(0, 0, mrg0, prg0)        // writes ats[0]
    A_STS_INV(1)                     // inv[1] for tile 1
    A_LDG_INV(2)                     // regs for STS in interval 0
    __syncthreads();                 // enter interval 0

    // ---- main pipeline: intervals 0..126 ----
    for (int it = 0; it < NIT - 2; it += 2) {
        A_INTERVAL(it,     0, 1, mrg1, prg1, mrg0, prg0)
        A_INTERVAL(it + 1, 1, 0, mrg0, prg0, mrg1, prg1)
    }
    A_INTERVAL(NIT - 2, 0, 1, mrg1, prg1, mrg0, prg0)   // interval 126
    A_MMA(1)                                             // tile 127

    // ---- epilogue: fragments -> g_pre ----
    #pragma unroll
    for (int m = 0; m < 2; m++) {
        const int q = q0 + wq * 32 + m * 16 + (lane >> 2);
        #pragma unroll
        for (int n = 0; n < 8; n++) {
            const int d = wd * 64 + n * 8 + ((lane & 3) << 1);
            *(float2*)&g_pre[(bS + q) * Dn + d] =
                make_float2(acc[m][n][0], acc[m][n][1]);
            *(float2*)&g_pre[(bS + q + 8) * Dn + d] =
                make_float2(acc[m][n][2], acc[m][n][3]);
        }
    }
}

// ============================================================
extern "C" void kernel_launch(void* const* d_in, const int* in_sizes, int n_in,
                              void* d_out, int out_size)
{
    const float* v       = (const float*)d_in[0];
    const float* k       = (const float*)d_in[1];
    const float* q       = (const float*)d_in[2];
    const float* mask    = (const float*)d_in[3];
    const float* wq_k    = (const float*)d_in[4];
    const float* wq_b    = (const float*)d_in[5];
    const float* wk_k    = (const float*)d_in[6];
    const float* wk_b    = (const float*)d_in[7];
    const float* wv_k    = (const float*)d_in[8];
    const float* wv_b    = (const float*)d_in[9];
    const float* anchor  = (const float*)d_in[10];
    const float* dense_k = (const float*)d_in[11];
    const float* dense_b = (const float*)d_in[12];

    float* out  = (float*)d_out;                      // [B,S,D]
    float* attn = out + (size_t)Mrows * Dn;           // [B,S,S]

    void *p_vph, *p_pre, *p_sq, *p_sk;
    cudaGetSymbolAddress(&p_vph, g_vph);
    cudaGetSymbolAddress(&p_pre, g_pre);
    cudaGetSymbolAddress(&p_sq,  g_sqbits);
    cudaGetSymbolAddress(&p_sk,  g_skbits);

    wsplit_kernel<<<256, 256>>>(wq_k, wk_k, wv_k, dense_k);

    proj_mma<<<dim3(Dn / 128, Mrows / 128, 3), 256>>>(
        q, k, v, wq_b, wk_b, wv_b,
        (unsigned*)p_sq, (unsigned*)p_sk, (__half*)p_vph);

    psum_kernel<<<dim3(Sn / 32, 4, Bn), 256>>>();
    attn_mma_kernel<<<dim3(Sn / 64, Bn), 256>>>(mask, attn);

    dense_mma<<<dim3(Dn / 128, Mrows / 128), 256>>>(
        (const float*)p_pre, dense_b, out, anchor);
}